// round 15
// baseline (speedup 1.0000x reference)
#include <cuda_runtime.h>
#include <cuda_fp16.h>
#include <math.h>
#include <stdint.h>

#define BATCH 4
#define T 2048
#define H 1024
#define NHEAD 16
#define HD 64
#define FF 4096
#define BT (BATCH * T)   // 8192 rows

// ---------------- scratch (allocation-free: __device__ globals) --------------
__device__ __half g_q[BT * H];     // fp16, d-perm16, pre-scaled log2e/32
__device__ __half g_k[BT * H];     // fp16, d-perm16
__device__ __half g_vt[BT * H];    // V^T: [b][h][d][T], fp16, key-perm16
__device__ float  g_x1[BT * H];    // x + attn_out (exact fp32)
__device__ __half g_x1r[BT * H];   // fp16, k-perm16 x1
__device__ __half g_xr[BT * H];    // fp16, k-perm16 x
__device__ __half g_h[BT * FF];    // fp16, k-perm16 gelu(x1@W1+b1)
__device__ __half g_wqt[H * H];    // transposed + fp16 + k-perm16 weights [N,K]
__device__ __half g_wkt[H * H];
__device__ __half g_wvt[H * H];
__device__ __half g_w1t[H * FF];   // [FF, H]
__device__ __half g_w2t[FF * H];   // [H, FF]

// ---------------- helpers ----------------------------------------------------
__device__ __forceinline__ uint32_t smem_u32(const void* p) {
    uint32_t a;
    asm("{ .reg .u64 t; cvta.to.shared.u64 t, %1; cvt.u32.u64 %0, t; }"
        : "=r"(a) : "l"(p));
    return a;
}
__device__ __forceinline__ float ftanh(float x) {
    float y;
    asm("tanh.approx.f32 %0, %1;" : "=f"(y) : "f"(x));
    return y;
}
__device__ __forceinline__ float fex2(float x) {
    float y;
    asm("ex2.approx.f32 %0, %1;" : "=f"(y) : "f"(x));
    return y;
}
__device__ __forceinline__ float gelu_f(float x) {
    return 0.5f * x * (1.0f + ftanh(0.7978845608028654f * (x + 0.044715f * x * x * x)));
}
// quad-interleave: logical k index l (0..15) -> physical position
// layout [0,1,8,9, 2,3,10,11, 4,5,12,13, 6,7,14,15]
__device__ __forceinline__ int perm16(int l) {
    return 4 * ((l & 7) >> 1) + 2 * (l >> 3) + (l & 1);
}
__device__ __forceinline__ uint32_t h2(float a, float b) {
    __half2 v = __floats2half2_rn(a, b);
    return *reinterpret_cast<uint32_t*>(&v);
}
__device__ __forceinline__ uint2 lds64(uint32_t addr) {
    uint2 v;
    asm volatile("ld.shared.v2.b32 {%0, %1}, [%2];" : "=r"(v.x), "=r"(v.y) : "r"(addr));
    return v;
}
__device__ __forceinline__ void mma16(float* d, uint32_t a0, uint32_t a1, uint32_t a2,
                                      uint32_t a3, uint32_t b0, uint32_t b1) {
    asm volatile(
        "mma.sync.aligned.m16n8k16.row.col.f32.f16.f16.f32 "
        "{%0,%1,%2,%3}, {%4,%5,%6,%7}, {%8,%9}, {%0,%1,%2,%3};"
        : "+f"(d[0]), "+f"(d[1]), "+f"(d[2]), "+f"(d[3])
        : "r"(a0), "r"(a1), "r"(a2), "r"(a3), "r"(b0), "r"(b1));
}

// ---------------- prep kernels ------------------------------------------------
__global__ void round_perm_k(const float* __restrict__ in, __half* __restrict__ out, int n) {
    int i = (blockIdx.x * blockDim.x + threadIdx.x) * 16;
    if (i < n) {
        float f[16];
        #pragma unroll
        for (int j = 0; j < 4; j++)
            *(float4*)(f + 4 * j) = *(const float4*)(in + i + 4 * j);
        uint4 a, b;
        a.x = h2(f[0], f[1]);   a.y = h2(f[8], f[9]);
        a.z = h2(f[2], f[3]);   a.w = h2(f[10], f[11]);
        b.x = h2(f[4], f[5]);   b.y = h2(f[12], f[13]);
        b.z = h2(f[6], f[7]);   b.w = h2(f[14], f[15]);
        *(uint4*)(out + i)     = a;
        *(uint4*)(out + i + 8) = b;
    }
}

__global__ void transpose_all(const float* __restrict__ Wq, const float* __restrict__ Wk,
                              const float* __restrict__ Wv, const float* __restrict__ W1,
                              const float* __restrict__ W2,
                              __half* __restrict__ wqt, __half* __restrict__ wkt,
                              __half* __restrict__ wvt, __half* __restrict__ w1t,
                              __half* __restrict__ w2t)
{
    __shared__ float t[32][33];
    const int bid = blockIdx.x;
    const float* W; __half* Wt; int K, N, tile;
    if (bid < 1024)      { W = Wq; Wt = wqt; K = H;  N = H;  tile = bid; }
    else if (bid < 2048) { W = Wk; Wt = wkt; K = H;  N = H;  tile = bid - 1024; }
    else if (bid < 3072) { W = Wv; Wt = wvt; K = H;  N = H;  tile = bid - 2048; }
    else if (bid < 7168) { W = W1; Wt = w1t; K = H;  N = FF; tile = bid - 3072; }
    else                 { W = W2; Wt = w2t; K = FF; N = H;  tile = bid - 7168; }
    const int ntx = N >> 5;
    const int n0 = (tile % ntx) * 32, k0 = (tile / ntx) * 32;
    const int tx = threadIdx.x, ty = threadIdx.y;
    #pragma unroll
    for (int j = ty; j < 32; j += 8)
        t[j][tx] = W[(size_t)(k0 + j) * N + n0 + tx];
    __syncthreads();
    const int kk = k0 + tx;
    const int kphys = (kk & ~15) + perm16(kk & 15);
    #pragma unroll
    for (int j = ty; j < 32; j += 8)
        Wt[(size_t)(n0 + j) * K + kphys] = __float2half_rn(t[tx][j]);
}

// ---------------- fp16 mma.sync GEMM ------------------------------------------
// CTA 128x256, 256 threads, warp tile 64x64. BK=128 per barrier (2 sub-stages),
// 2 stages, lookahead 1.
// modes: 1 gelu->fp16 perm, 2 float+res, 3 q/k fp16 perm (z0 scaled log2e/32; z2 -> VT)
#define SUB_BYTES   49152                 // 16KB A + 32KB B (one BK=64 sub-stage)
#define STAGE_BYTES (2 * SUB_BYTES)       // 98304 (BK=128)
#define GEMM_SMEM   (2 * STAGE_BYTES)     // 196608

__global__ __launch_bounds__(256, 1)
void gemm_fp16(const __half* __restrict__ A,
               const __half* __restrict__ B0t, const __half* __restrict__ B1t,
               const __half* __restrict__ B2t,
               const float* __restrict__ bias0, const float* __restrict__ bias1,
               const float* __restrict__ bias2,
               void* __restrict__ C0, void* __restrict__ C1, void* __restrict__ C2,
               const float* __restrict__ res, __half* __restrict__ vt,
               int K, int N, int mode)
{
    extern __shared__ char sf[];
    const uint32_t sbase = smem_u32(sf);

    const __half* Bt = B0t; const float* bias = bias0; void* Cp = C0;
    if (blockIdx.z == 1) { Bt = B1t; bias = bias1; Cp = C1; }
    else if (blockIdx.z == 2) { Bt = B2t; bias = bias2; Cp = C2; }
    int emode = mode;
    float oscale = 1.0f;
    if (mode == 3) {
        if (blockIdx.z == 2) emode = 4;
        else if (blockIdx.z == 0) oscale = 0.045084235f;   // log2(e)/32
    }

    const int tid  = threadIdx.x;
    const int lane = tid & 31;
    const int w    = tid >> 5;
    const int g    = lane >> 2;
    const int c    = lane & 3;
    const int wm   = w & 1;
    const int wn   = w >> 1;
    const int bx = blockIdx.x, by = blockIdx.y;
    const int nk2 = K >> 7;          // BK=128 iterations

    const int lrow = tid >> 3;
    const int cj   = tid & 7;
    const uint32_t sA = (uint32_t)(lrow * 128 + ((cj ^ (lrow & 7)) << 4));
    const __half* gA = A  + (size_t)(by * 128 + lrow) * K + cj * 8;
    const __half* gB = Bt + (size_t)(bx * 256 + lrow) * K + cj * 8;

    // prologue: load stage 0 (both 64-k halves)
    #pragma unroll
    for (int hh = 0; hh < 2; hh++) {
        const uint32_t sb = sbase + hh * SUB_BYTES;
        const int ko = hh * 64;
        #pragma unroll
        for (int t = 0; t < 4; t++)
            asm volatile("cp.async.cg.shared.global [%0], [%1], 16;"
                         :: "r"(sb + sA + t * 4096),
                            "l"(gA + (size_t)(32 * t) * K + ko) : "memory");
        #pragma unroll
        for (int u = 0; u < 8; u++)
            asm volatile("cp.async.cg.shared.global [%0], [%1], 16;"
                         :: "r"(sb + 16384 + sA + u * 4096),
                            "l"(gB + (size_t)(32 * u) * K + ko) : "memory");
    }
    asm volatile("cp.async.commit_group;" ::: "memory");

    float acc[4][8][4];
    #pragma unroll
    for (int mi = 0; mi < 4; mi++)
        #pragma unroll
        for (int ni = 0; ni < 8; ni++)
            #pragma unroll
            for (int r = 0; r < 4; r++) acc[mi][ni][r] = 0.0f;

    const uint32_t abase = (uint32_t)((wm * 64 + g) * 128);
    const uint32_t bbase = (uint32_t)(16384 + (wn * 64 + g) * 128);
    uint32_t coff[4];
    #pragma unroll
    for (int s = 0; s < 4; s++)
        coff[s] = (uint32_t)((((2 * s + (c >> 1)) ^ g) << 4) + (c & 1) * 8);

    for (int i = 0; i < nk2; i++) {
        asm volatile("cp.async.wait_group 0;" ::: "memory");
        __syncthreads();

        const int j = i + 1;
        if (j < nk2) {
            const uint32_t sbj = sbase + (j & 1) * STAGE_BYTES;
            #pragma unroll
            for (int hh = 0; hh < 2; hh++) {
                const uint32_t sb = sbj + hh * SUB_BYTES;
                const int ko = j * 128 + hh * 64;
                #pragma unroll
                for (int t = 0; t < 4; t++)
                    asm volatile("cp.async.cg.shared.global [%0], [%1], 16;"
                                 :: "r"(sb + sA + t * 4096),
                                    "l"(gA + (size_t)(32 * t) * K + ko) : "memory");
                #pragma unroll
                for (int u = 0; u < 8; u++)
                    asm volatile("cp.async.cg.shared.global [%0], [%1], 16;"
                                 :: "r"(sb + 16384 + sA + u * 4096),
                                    "l"(gB + (size_t)(32 * u) * K + ko) : "memory");
            }
        }
        asm volatile("cp.async.commit_group;" ::: "memory");

        const uint32_t sbi = sbase + (i & 1) * STAGE_BYTES;
        #pragma unroll
        for (int hh = 0; hh < 2; hh++) {
            const uint32_t sb = sbi + hh * SUB_BYTES;
            #pragma unroll
            for (int s = 0; s < 4; s++) {
                const uint32_t off = coff[s];
                uint2 av[4][2];
                #pragma unroll
                for (int mi = 0; mi < 4; mi++) {
                    av[mi][0] = lds64(sb + abase + mi * 2048 + off);
                    av[mi][1] = lds64(sb + abase + mi * 2048 + 1024 + off);
                }
                uint2 bv[8];
                #pragma unroll
                for (int ni = 0; ni < 8; ni++)
                    bv[ni] = lds64(sb + bbase + ni * 1024 + off);
                #pragma unroll
                for (int mi = 0; mi < 4; mi++)
                    #pragma unroll
                    for (int ni = 0; ni < 8; ni++)
                        mma16(acc[mi][ni],
                              av[mi][0].x, av[mi][1].x, av[mi][0].y, av[mi][1].y,
                              bv[ni].x, bv[ni].y);
            }
        }
    }

    // ---- epilogue ----
    #pragma unroll
    for (int mi = 0; mi < 4; mi++) {
        const int r0 = by * 128 + wm * 64 + mi * 16 + g;
        #pragma unroll
        for (int ni = 0; ni < 8; ni++) {
            const int colg = bx * 256 + wn * 64 + ni * 8;
            const float bb0 = bias[colg + 2 * c];
            const float bb1 = bias[colg + 2 * c + 1];
            float v00 = acc[mi][ni][0] + bb0;
            float v01 = acc[mi][ni][1] + bb1;
            float v10 = acc[mi][ni][2] + bb0;
            float v11 = acc[mi][ni][3] + bb1;
            if (emode == 1) {
                v00 = gelu_f(v00); v01 = gelu_f(v01);
                v10 = gelu_f(v10); v11 = gelu_f(v11);
            }
            if (emode == 2) {
                float* C = (float*)Cp;
                const float* rr0 = res + (size_t)r0 * N + colg + 2 * c;
                const float* rr1 = res + (size_t)(r0 + 8) * N + colg + 2 * c;
                float2 o0; o0.x = v00 + rr0[0]; o0.y = v01 + rr0[1];
                float2 o1; o1.x = v10 + rr1[0]; o1.y = v11 + rr1[1];
                *(float2*)(C + (size_t)r0 * N + colg + 2 * c) = o0;
                *(float2*)(C + (size_t)(r0 + 8) * N + colg + 2 * c) = o1;
            } else if (emode == 4) {
                // V^T: [b][h][d][T], token perm16'd within 16-groups
                const int col0 = colg + 2 * c;          // channel (even)
                const int b0   = r0 >> 11;
                const int head = col0 >> 6;
                const int d    = col0 & 63;
                const int t16  = (r0 & 2047) & ~15;
                const int tpp  = 4 * (g >> 1) + (g & 1);   // perm16(g), g<8
                __half* vb = vt + ((size_t)(b0 * 16 + head) * 64 + d) * 2048 + t16 + tpp;
                vb[0]        = __float2half_rn(v00);    // (d,   token r0)
                vb[2048]     = __float2half_rn(v01);    // (d+1, token r0)
                vb[2]        = __float2half_rn(v10);    // (d,   token r0+8): perm16(g+8)=tpp+2
                vb[2048 + 2] = __float2half_rn(v11);
            } else {
                // fp16 + perm16 column store (emode 1 or 3)
                v00 *= oscale; v01 *= oscale; v10 *= oscale; v11 *= oscale;
                __half* C = (__half*)Cp;
                const int base16 = colg & ~15;
                const int poff = 4 * c + 2 * (ni & 1);
                *(uint32_t*)(C + (size_t)r0 * N + base16 + poff)       = h2(v00, v01);
                *(uint32_t*)(C + (size_t)(r0 + 8) * N + base16 + poff) = h2(v10, v11);
            }
        }
    }
}

// ---------------- fp16 tensor-core flash attention + residual ------------------
// 128 q-rows per CTA, 8 warps. TWO key-tiles (128 keys) per barrier window.
// K buffers: 128 key-rows x 128B (two 8KB tiles stacked by key-half).
// VT buffers: 64 d-rows x 256B window = two 8KB tiles stacked by TOKEN-half.
// No online max; p = exp2(S); P in registers.
// smem: K buf0@0, buf1@16384 | VT buf0@32768, buf1@49152 -> 64KB
#define AK0  0
#define AVT0 32768
#define ATT_SMEM 65536

__global__ __launch_bounds__(256, 2)
void attn_kernel(const float* __restrict__ x, float* __restrict__ x1,
                 __half* __restrict__ x1r)
{
    extern __shared__ char sm[];
    const uint32_t sbase = smem_u32(sm);

    const int qt = gridDim.x - 1 - blockIdx.x;   // heavy tiles first
    const int bh = blockIdx.y;
    const int b = bh >> 4, h = bh & 15;
    const int tid = threadIdx.x, lane = tid & 31, w = tid >> 5;
    const int g = lane >> 2, c = lane & 3;

    const size_t headoff = (size_t)b * T * H + (size_t)h * HD;
    const __half* Qg  = g_q + headoff;
    const __half* Kg  = g_k + headoff;
    const __half* VTg = g_vt + (size_t)bh * HD * T;

    // K loader: 128 key-rows x 8 chunks; thread -> row tid>>1, chunks (tid&1)*4 ..+3
    const int krow = tid >> 1;            // 0..127
    const int kch0 = (tid & 1) * 4;
    uint32_t ksoA[4];
    #pragma unroll
    for (int i = 0; i < 4; i++) {
        const int ch = kch0 + i;
        ksoA[i] = (uint32_t)((krow >> 6) * 8192 + (krow & 63) * 128
                             + ((ch ^ (krow & 7)) << 4));
    }
    const __half* kgp = Kg + (size_t)krow * H + kch0 * 8;

    // VT loader: 64 d-rows x 16 chunks (256B window); thread -> row tid>>2,
    // chunks (tid&3)*4 ..+3; chunk>>3 selects token-half tile (8KB stride)
    const int vrow = tid >> 2;            // 0..63
    const int vch0 = (tid & 3) * 4;       // 0..15 range
    uint32_t vsoA[4];
    #pragma unroll
    for (int i = 0; i < 4; i++) {
        const int ch = vch0 + i;
        vsoA[i] = (uint32_t)((ch >> 3) * 8192 + vrow * 128
                             + (((ch & 7) ^ (vrow & 7)) << 4));
    }
    const __half* vtgp = VTg + (size_t)vrow * T + vch0 * 8;

    const int nkt2 = qt + 1;              // 128-key windows

    // prologue: load window 0
    #pragma unroll
    for (int i = 0; i < 4; i++) {
        asm volatile("cp.async.cg.shared.global [%0], [%1], 16;"
                     :: "r"(sbase + AK0 + ksoA[i]), "l"(kgp + i * 8) : "memory");
        asm volatile("cp.async.cg.shared.global [%0], [%1], 16;"
                     :: "r"(sbase + AVT0 + vsoA[i]), "l"(vtgp + i * 8) : "memory");
    }
    asm volatile("cp.async.commit_group;" ::: "memory");

    uint32_t qa[4][4];
    {
        const int r0 = qt * 128 + w * 16 + g;
        const __half* q0 = Qg + (size_t)r0 * H;
        #pragma unroll
        for (int s = 0; s < 4; s++) {
            uint2 t0 = *(const uint2*)(q0 + s * 16 + c * 4);
            uint2 t1 = *(const uint2*)(q0 + 8 * H + s * 16 + c * 4);
            qa[s][0] = t0.x; qa[s][1] = t1.x; qa[s][2] = t0.y; qa[s][3] = t1.y;
        }
    }

    float o[8][4];
    #pragma unroll
    for (int nt = 0; nt < 8; nt++)
        #pragma unroll
        for (int r = 0; r < 4; r++) o[nt][r] = 0.0f;
    float ls0 = 0.0f, ls1 = 0.0f;

    const int rowlo = qt * 128 + w * 16;
    const int row0 = rowlo + g;
    uint32_t coff[4];
    #pragma unroll
    for (int s = 0; s < 4; s++)
        coff[s] = (uint32_t)((((2 * s + (c >> 1)) ^ g) << 4) + (c & 1) * 8);

    for (int kt2 = 0; kt2 < nkt2; kt2++) {
        const uint32_t buf = (kt2 & 1) ? 16384u : 0u;
        asm volatile("cp.async.wait_group 0;" ::: "memory");
        __syncthreads();

        if (kt2 + 1 < nkt2) {
            const uint32_t nb = (kt2 & 1) ? 0u : 16384u;
            const __half* ks = kgp  + (size_t)(kt2 + 1) * 128 * H;
            const __half* vs = vtgp + (kt2 + 1) * 128;
            #pragma unroll
            for (int i = 0; i < 4; i++) {
                asm volatile("cp.async.cg.shared.global [%0], [%1], 16;"
                             :: "r"(sbase + AK0 + nb + ksoA[i]), "l"(ks + i * 8) : "memory");
                asm volatile("cp.async.cg.shared.global [%0], [%1], 16;"
                             :: "r"(sbase + AVT0 + nb + vsoA[i]), "l"(vs + i * 8) : "memory");
            }
        }
        asm volatile("cp.async.commit_group;" ::: "memory");

        #pragma unroll
        for (int half = 0; half < 2; half++) {
            const int ktbase = kt2 * 128 + half * 64;
            if (ktbase > rowlo + 15) break;
            const uint32_t kbuf  = sbase + AK0 + buf + half * 8192;
            const uint32_t vtbuf = sbase + AVT0 + buf + half * 8192;

            // S = Q @ K^T (S pre-scaled by log2e via q)
            float sacc[8][4];
            #pragma unroll
            for (int nt = 0; nt < 8; nt++)
                #pragma unroll
                for (int r = 0; r < 4; r++) sacc[nt][r] = 0.0f;
            #pragma unroll
            for (int s = 0; s < 4; s++) {
                uint2 bf[8];
                #pragma unroll
                for (int nt = 0; nt < 8; nt++)
                    bf[nt] = lds64(kbuf + (uint32_t)((nt * 8 + g) * 128) + coff[s]);
                #pragma unroll
                for (int nt = 0; nt < 8; nt++)
                    mma16(sacc[nt], qa[s][0], qa[s][1], qa[s][2], qa[s][3],
                          bf[nt].x, bf[nt].y);
            }

            if (ktbase + 63 > rowlo) {
                #pragma unroll
                for (int nt = 0; nt < 8; nt++) {
                    const int colb = ktbase + nt * 8 + 2 * c;
                    if (colb     > row0)     sacc[nt][0] = -1e30f;
                    if (colb + 1 > row0)     sacc[nt][1] = -1e30f;
                    if (colb     > row0 + 8) sacc[nt][2] = -1e30f;
                    if (colb + 1 > row0 + 8) sacc[nt][3] = -1e30f;
                }
            }

            // p = exp2(S); pack straight into A-fragment registers
            uint32_t pa[8][2];
            #pragma unroll
            for (int nt = 0; nt < 8; nt++) {
                const float p00 = fex2(sacc[nt][0]);
                const float p01 = fex2(sacc[nt][1]);
                const float p10 = fex2(sacc[nt][2]);
                const float p11 = fex2(sacc[nt][3]);
                ls0 += p00 + p01;
                ls1 += p10 + p11;
                pa[nt][0] = h2(p00, p01);
                pa[nt][1] = h2(p10, p11);
            }

            // O += P @ V  (P from registers, V^T B-fragments from smem)
            #pragma unroll
            for (int kb = 0; kb < 4; kb++) {
                const uint32_t a0 = pa[2 * kb][0];
                const uint32_t a1 = pa[2 * kb][1];
                const uint32_t a2 = pa[2 * kb + 1][0];
                const uint32_t a3 = pa[2 * kb + 1][1];
                #pragma unroll
                for (int nt = 0; nt < 8; nt++) {
                    const uint2 vb = lds64(vtbuf + (uint32_t)((nt * 8 + g) * 128) + coff[kb]);
                    mma16(o[nt], a0, a1, a2, a3, vb.x, vb.y);
                }
            }
        }
    }

    // single end-of-kernel row-sum reduction (quad lanes share rows)
    ls0 += __shfl_xor_sync(0xffffffffu, ls0, 1);
    ls0 += __shfl_xor_sync(0xffffffffu, ls0, 2);
    ls1 += __shfl_xor_sync(0xffffffffu, ls1, 1);
    ls1 += __shfl_xor_sync(0xffffffffu, ls1, 2);

    // epilogue: x1 = x + O/l (fp32 exact), x1r = fp16 perm16
    const float inv0 = 1.0f / ls0;
    const float inv1 = 1.0f / ls1;
    const size_t rb0 = (size_t)b * T * H + (size_t)row0 * H + (size_t)h * HD;
    const size_t rb1 = rb0 + 8 * H;
    #pragma unroll
    for (int nt = 0; nt < 8; nt++) {
        const int d0 = nt * 8 + 2 * c;
        const float v00 = o[nt][0] * inv0 + x[rb0 + d0];
        const float v01 = o[nt][1] * inv0 + x[rb0 + d0 + 1];
        const float v10 = o[nt][2] * inv1 + x[rb1 + d0];
        const float v11 = o[nt][3] * inv1 + x[rb1 + d0 + 1];
        float2 t0; t0.x = v00; t0.y = v01;
        float2 t1; t1.x = v10; t1.y = v11;
        *(float2*)(x1 + rb0 + d0) = t0;
        *(float2*)(x1 + rb1 + d0) = t1;
        const int poff = (nt >> 1) * 16 + 4 * c + 2 * (nt & 1);
        *(uint32_t*)(x1r + rb0 + poff) = h2(v00, v01);
        *(uint32_t*)(x1r + rb1 + poff) = h2(v10, v11);
    }
}

// ---------------- launch -----------------------------------------------------
extern "C" void kernel_launch(void* const* d_in, const int* in_sizes, int n_in,
                              void* d_out, int out_size)
{
    const float* x  = (const float*)d_in[0];
    const float* Wq = (const float*)d_in[1];
    const float* bq = (const float*)d_in[2];
    const float* Wk = (const float*)d_in[3];
    const float* bk = (const float*)d_in[4];
    const float* Wv = (const float*)d_in[5];
    const float* bv = (const float*)d_in[6];
    const float* W1 = (const float*)d_in[7];
    const float* b1 = (const float*)d_in[8];
    const float* W2 = (const float*)d_in[9];
    const float* b2 = (const float*)d_in[10];
    float* out = (float*)d_out;

    __half *q, *k, *vt, *x1r, *xr, *h, *wqt, *wkt, *wvt, *w1t, *w2t;
    float *x1;
    cudaGetSymbolAddress((void**)&q,    g_q);
    cudaGetSymbolAddress((void**)&k,    g_k);
    cudaGetSymbolAddress((void**)&vt,   g_vt);
    cudaGetSymbolAddress((void**)&x1,   g_x1);
    cudaGetSymbolAddress((void**)&x1r,  g_x1r);
    cudaGetSymbolAddress((void**)&xr,   g_xr);
    cudaGetSymbolAddress((void**)&h,    g_h);
    cudaGetSymbolAddress((void**)&wqt,  g_wqt);
    cudaGetSymbolAddress((void**)&wkt,  g_wkt);
    cudaGetSymbolAddress((void**)&wvt,  g_wvt);
    cudaGetSymbolAddress((void**)&w1t,  g_w1t);
    cudaGetSymbolAddress((void**)&w2t,  g_w2t);

    round_perm_k<<<(BT * H) / (256 * 16), 256>>>(x, xr, BT * H);
    transpose_all<<<11264, dim3(32, 8)>>>(Wq, Wk, Wv, W1, W2, wqt, wkt, wvt, w1t, w2t);

    cudaFuncSetAttribute(gemm_fp16, cudaFuncAttributeMaxDynamicSharedMemorySize, GEMM_SMEM);

    // QKV (q: fp16 perm + log2e/32 scale; k: fp16 perm; v -> V^T fp16)
    gemm_fp16<<<dim3(H / 256, BT / 128, 3), 256, GEMM_SMEM>>>(
        xr, wqt, wkt, wvt, bq, bk, bv, q, k, nullptr, nullptr, vt, H, H, 3);

    cudaFuncSetAttribute(attn_kernel, cudaFuncAttributeMaxDynamicSharedMemorySize, ATT_SMEM);
    attn_kernel<<<dim3(T / 128, BATCH * NHEAD), 256, ATT_SMEM>>>(x, x1, x1r);

    // MLP1: h = fp16(gelu(x1r @ W1t^T + b1)), perm16 cols
    gemm_fp16<<<dim3(FF / 256, BT / 128, 1), 256, GEMM_SMEM>>>(
        x1r, w1t, w1t, w1t, b1, b1, b1, h, h, h, nullptr, nullptr, H, FF, 1);

    // MLP2: out = h @ W2t^T + b2 + x1  (fp32 out)
    gemm_fp16<<<dim3(H / 256, BT / 128, 1), 256, GEMM_SMEM>>>(
        h, w2t, w2t, w2t, b2, b2, b2, out, out, out, x1, nullptr, FF, H, 2);
}

// round 16
// speedup vs baseline: 1.0159x; 1.0159x over previous
#include <cuda_runtime.h>
#include <cuda_fp16.h>
#include <math.h>
#include <stdint.h>

#define BATCH 4
#define T 2048
#define H 1024
#define NHEAD 16
#define HD 64
#define FF 4096
#define BT (BATCH * T)   // 8192 rows

// ---------------- scratch (allocation-free: __device__ globals) --------------
__device__ __half g_q[BT * H];     // fp16, d-perm16, pre-scaled log2e/32
__device__ __half g_k[BT * H];     // fp16, d-perm16
__device__ __half g_vt[BT * H];    // V^T: [b][h][d][T], fp16, key-perm16
__device__ float  g_x1[BT * H];    // x + attn_out (exact fp32)
__device__ __half g_x1r[BT * H];   // fp16, k-perm16 x1
__device__ __half g_xr[BT * H];    // fp16, k-perm16 x
__device__ __half g_h[BT * FF];    // fp16, k-perm16 gelu(x1@W1+b1)
__device__ __half g_wqt[H * H];    // transposed + fp16 + k-perm16 weights [N,K]
__device__ __half g_wkt[H * H];
__device__ __half g_wvt[H * H];
__device__ __half g_w1t[H * FF];   // [FF, H]
__device__ __half g_w2t[FF * H];   // [H, FF]

// ---------------- helpers ----------------------------------------------------
__device__ __forceinline__ uint32_t smem_u32(const void* p) {
    uint32_t a;
    asm("{ .reg .u64 t; cvta.to.shared.u64 t, %1; cvt.u32.u64 %0, t; }"
        : "=r"(a) : "l"(p));
    return a;
}
__device__ __forceinline__ float ftanh(float x) {
    float y;
    asm("tanh.approx.f32 %0, %1;" : "=f"(y) : "f"(x));
    return y;
}
__device__ __forceinline__ float gelu_f(float x) {
    return 0.5f * x * (1.0f + ftanh(0.7978845608028654f * (x + 0.044715f * x * x * x)));
}
// quad-interleave: logical k index l (0..15) -> physical position
// layout [0,1,8,9, 2,3,10,11, 4,5,12,13, 6,7,14,15]
__device__ __forceinline__ int perm16(int l) {
    return 4 * ((l & 7) >> 1) + 2 * (l >> 3) + (l & 1);
}
__device__ __forceinline__ uint32_t h2(float a, float b) {
    __half2 v = __floats2half2_rn(a, b);
    return *reinterpret_cast<uint32_t*>(&v);
}
// pack two f32 -> f16x2 (lo = a, hi = b)
__device__ __forceinline__ uint32_t cvt_f16x2(float a, float b) {
    uint32_t r;
    asm("cvt.rn.f16x2.f32 %0, %1, %2;" : "=r"(r) : "f"(b), "f"(a));
    return r;
}
__device__ __forceinline__ uint32_t ex2_h2(uint32_t x) {
    uint32_t y;
    asm("ex2.approx.f16x2 %0, %1;" : "=r"(y) : "r"(x));
    return y;
}
__device__ __forceinline__ uint2 lds64(uint32_t addr) {
    uint2 v;
    asm volatile("ld.shared.v2.b32 {%0, %1}, [%2];" : "=r"(v.x), "=r"(v.y) : "r"(addr));
    return v;
}
__device__ __forceinline__ void mma16(float* d, uint32_t a0, uint32_t a1, uint32_t a2,
                                      uint32_t a3, uint32_t b0, uint32_t b1) {
    asm volatile(
        "mma.sync.aligned.m16n8k16.row.col.f32.f16.f16.f32 "
        "{%0,%1,%2,%3}, {%4,%5,%6,%7}, {%8,%9}, {%0,%1,%2,%3};"
        : "+f"(d[0]), "+f"(d[1]), "+f"(d[2]), "+f"(d[3])
        : "r"(a0), "r"(a1), "r"(a2), "r"(a3), "r"(b0), "r"(b1));
}

// ---------------- prep kernels ------------------------------------------------
__global__ void round_perm_k(const float* __restrict__ in, __half* __restrict__ out, int n) {
    int i = (blockIdx.x * blockDim.x + threadIdx.x) * 16;
    if (i < n) {
        float f[16];
        #pragma unroll
        for (int j = 0; j < 4; j++)
            *(float4*)(f + 4 * j) = *(const float4*)(in + i + 4 * j);
        uint4 a, b;
        a.x = h2(f[0], f[1]);   a.y = h2(f[8], f[9]);
        a.z = h2(f[2], f[3]);   a.w = h2(f[10], f[11]);
        b.x = h2(f[4], f[5]);   b.y = h2(f[12], f[13]);
        b.z = h2(f[6], f[7]);   b.w = h2(f[14], f[15]);
        *(uint4*)(out + i)     = a;
        *(uint4*)(out + i + 8) = b;
    }
}

__global__ void transpose_all(const float* __restrict__ Wq, const float* __restrict__ Wk,
                              const float* __restrict__ Wv, const float* __restrict__ W1,
                              const float* __restrict__ W2,
                              __half* __restrict__ wqt, __half* __restrict__ wkt,
                              __half* __restrict__ wvt, __half* __restrict__ w1t,
                              __half* __restrict__ w2t)
{
    __shared__ float t[32][33];
    const int bid = blockIdx.x;
    const float* W; __half* Wt; int K, N, tile;
    if (bid < 1024)      { W = Wq; Wt = wqt; K = H;  N = H;  tile = bid; }
    else if (bid < 2048) { W = Wk; Wt = wkt; K = H;  N = H;  tile = bid - 1024; }
    else if (bid < 3072) { W = Wv; Wt = wvt; K = H;  N = H;  tile = bid - 2048; }
    else if (bid < 7168) { W = W1; Wt = w1t; K = H;  N = FF; tile = bid - 3072; }
    else                 { W = W2; Wt = w2t; K = FF; N = H;  tile = bid - 7168; }
    const int ntx = N >> 5;
    const int n0 = (tile % ntx) * 32, k0 = (tile / ntx) * 32;
    const int tx = threadIdx.x, ty = threadIdx.y;
    #pragma unroll
    for (int j = ty; j < 32; j += 8)
        t[j][tx] = W[(size_t)(k0 + j) * N + n0 + tx];
    __syncthreads();
    const int kk = k0 + tx;
    const int kphys = (kk & ~15) + perm16(kk & 15);
    #pragma unroll
    for (int j = ty; j < 32; j += 8)
        Wt[(size_t)(n0 + j) * K + kphys] = __float2half_rn(t[tx][j]);
}

// ---------------- fp16 mma.sync GEMM ------------------------------------------
// CTA 128x256, 256 threads, warp tile 64x64. BK=128 per barrier (2 sub-stages),
// 2 stages, lookahead 1.
// modes: 1 gelu->fp16 perm, 2 float+res, 3 q/k fp16 perm (z0 scaled log2e/32; z2 -> VT)
#define SUB_BYTES   49152                 // 16KB A + 32KB B (one BK=64 sub-stage)
#define STAGE_BYTES (2 * SUB_BYTES)       // 98304 (BK=128)
#define GEMM_SMEM   (2 * STAGE_BYTES)     // 196608

__global__ __launch_bounds__(256, 1)
void gemm_fp16(const __half* __restrict__ A,
               const __half* __restrict__ B0t, const __half* __restrict__ B1t,
               const __half* __restrict__ B2t,
               const float* __restrict__ bias0, const float* __restrict__ bias1,
               const float* __restrict__ bias2,
               void* __restrict__ C0, void* __restrict__ C1, void* __restrict__ C2,
               const float* __restrict__ res, __half* __restrict__ vt,
               int K, int N, int mode)
{
    extern __shared__ char sf[];
    const uint32_t sbase = smem_u32(sf);

    const __half* Bt = B0t; const float* bias = bias0; void* Cp = C0;
    if (blockIdx.z == 1) { Bt = B1t; bias = bias1; Cp = C1; }
    else if (blockIdx.z == 2) { Bt = B2t; bias = bias2; Cp = C2; }
    int emode = mode;
    float oscale = 1.0f;
    if (mode == 3) {
        if (blockIdx.z == 2) emode = 4;
        else if (blockIdx.z == 0) oscale = 0.045084235f;   // log2(e)/32
    }

    const int tid  = threadIdx.x;
    const int lane = tid & 31;
    const int w    = tid >> 5;
    const int g    = lane >> 2;
    const int c    = lane & 3;
    const int wm   = w & 1;
    const int wn   = w >> 1;
    const int bx = blockIdx.x, by = blockIdx.y;
    const int nk2 = K >> 7;          // BK=128 iterations

    const int lrow = tid >> 3;
    const int cj   = tid & 7;
    const uint32_t sA = (uint32_t)(lrow * 128 + ((cj ^ (lrow & 7)) << 4));
    const __half* gA = A  + (size_t)(by * 128 + lrow) * K + cj * 8;
    const __half* gB = Bt + (size_t)(bx * 256 + lrow) * K + cj * 8;

    // prologue: load stage 0 (both 64-k halves)
    #pragma unroll
    for (int hh = 0; hh < 2; hh++) {
        const uint32_t sb = sbase + hh * SUB_BYTES;
        const int ko = hh * 64;
        #pragma unroll
        for (int t = 0; t < 4; t++)
            asm volatile("cp.async.cg.shared.global [%0], [%1], 16;"
                         :: "r"(sb + sA + t * 4096),
                            "l"(gA + (size_t)(32 * t) * K + ko) : "memory");
        #pragma unroll
        for (int u = 0; u < 8; u++)
            asm volatile("cp.async.cg.shared.global [%0], [%1], 16;"
                         :: "r"(sb + 16384 + sA + u * 4096),
                            "l"(gB + (size_t)(32 * u) * K + ko) : "memory");
    }
    asm volatile("cp.async.commit_group;" ::: "memory");

    float acc[4][8][4];
    #pragma unroll
    for (int mi = 0; mi < 4; mi++)
        #pragma unroll
        for (int ni = 0; ni < 8; ni++)
            #pragma unroll
            for (int r = 0; r < 4; r++) acc[mi][ni][r] = 0.0f;

    const uint32_t abase = (uint32_t)((wm * 64 + g) * 128);
    const uint32_t bbase = (uint32_t)(16384 + (wn * 64 + g) * 128);
    uint32_t coff[4];
    #pragma unroll
    for (int s = 0; s < 4; s++)
        coff[s] = (uint32_t)((((2 * s + (c >> 1)) ^ g) << 4) + (c & 1) * 8);

    for (int i = 0; i < nk2; i++) {
        asm volatile("cp.async.wait_group 0;" ::: "memory");
        __syncthreads();

        const int j = i + 1;
        if (j < nk2) {
            const uint32_t sbj = sbase + (j & 1) * STAGE_BYTES;
            #pragma unroll
            for (int hh = 0; hh < 2; hh++) {
                const uint32_t sb = sbj + hh * SUB_BYTES;
                const int ko = j * 128 + hh * 64;
                #pragma unroll
                for (int t = 0; t < 4; t++)
                    asm volatile("cp.async.cg.shared.global [%0], [%1], 16;"
                                 :: "r"(sb + sA + t * 4096),
                                    "l"(gA + (size_t)(32 * t) * K + ko) : "memory");
                #pragma unroll
                for (int u = 0; u < 8; u++)
                    asm volatile("cp.async.cg.shared.global [%0], [%1], 16;"
                                 :: "r"(sb + 16384 + sA + u * 4096),
                                    "l"(gB + (size_t)(32 * u) * K + ko) : "memory");
            }
        }
        asm volatile("cp.async.commit_group;" ::: "memory");

        const uint32_t sbi = sbase + (i & 1) * STAGE_BYTES;
        #pragma unroll
        for (int hh = 0; hh < 2; hh++) {
            const uint32_t sb = sbi + hh * SUB_BYTES;
            #pragma unroll
            for (int s = 0; s < 4; s++) {
                const uint32_t off = coff[s];
                uint2 av[4][2];
                #pragma unroll
                for (int mi = 0; mi < 4; mi++) {
                    av[mi][0] = lds64(sb + abase + mi * 2048 + off);
                    av[mi][1] = lds64(sb + abase + mi * 2048 + 1024 + off);
                }
                uint2 bv[8];
                #pragma unroll
                for (int ni = 0; ni < 8; ni++)
                    bv[ni] = lds64(sb + bbase + ni * 1024 + off);
                #pragma unroll
                for (int mi = 0; mi < 4; mi++)
                    #pragma unroll
                    for (int ni = 0; ni < 8; ni++)
                        mma16(acc[mi][ni],
                              av[mi][0].x, av[mi][1].x, av[mi][0].y, av[mi][1].y,
                              bv[ni].x, bv[ni].y);
            }
        }
    }

    // ---- epilogue ----
    #pragma unroll
    for (int mi = 0; mi < 4; mi++) {
        const int r0 = by * 128 + wm * 64 + mi * 16 + g;
        #pragma unroll
        for (int ni = 0; ni < 8; ni++) {
            const int colg = bx * 256 + wn * 64 + ni * 8;
            const float bb0 = bias[colg + 2 * c];
            const float bb1 = bias[colg + 2 * c + 1];
            float v00 = acc[mi][ni][0] + bb0;
            float v01 = acc[mi][ni][1] + bb1;
            float v10 = acc[mi][ni][2] + bb0;
            float v11 = acc[mi][ni][3] + bb1;
            if (emode == 1) {
                v00 = gelu_f(v00); v01 = gelu_f(v01);
                v10 = gelu_f(v10); v11 = gelu_f(v11);
            }
            if (emode == 2) {
                float* C = (float*)Cp;
                const float* rr0 = res + (size_t)r0 * N + colg + 2 * c;
                const float* rr1 = res + (size_t)(r0 + 8) * N + colg + 2 * c;
                float2 o0; o0.x = v00 + rr0[0]; o0.y = v01 + rr0[1];
                float2 o1; o1.x = v10 + rr1[0]; o1.y = v11 + rr1[1];
                *(float2*)(C + (size_t)r0 * N + colg + 2 * c) = o0;
                *(float2*)(C + (size_t)(r0 + 8) * N + colg + 2 * c) = o1;
            } else if (emode == 4) {
                // V^T: [b][h][d][T], token perm16'd within 16-groups
                const int col0 = colg + 2 * c;          // channel (even)
                const int b0   = r0 >> 11;
                const int head = col0 >> 6;
                const int d    = col0 & 63;
                const int t16  = (r0 & 2047) & ~15;
                const int tpp  = 4 * (g >> 1) + (g & 1);   // perm16(g), g<8
                __half* vb = vt + ((size_t)(b0 * 16 + head) * 64 + d) * 2048 + t16 + tpp;
                vb[0]        = __float2half_rn(v00);    // (d,   token r0)
                vb[2048]     = __float2half_rn(v01);    // (d+1, token r0)
                vb[2]        = __float2half_rn(v10);    // (d,   token r0+8): perm16(g+8)=tpp+2
                vb[2048 + 2] = __float2half_rn(v11);
            } else {
                // fp16 + perm16 column store (emode 1 or 3)
                v00 *= oscale; v01 *= oscale; v10 *= oscale; v11 *= oscale;
                __half* C = (__half*)Cp;
                const int base16 = colg & ~15;
                const int poff = 4 * c + 2 * (ni & 1);
                *(uint32_t*)(C + (size_t)r0 * N + base16 + poff)       = h2(v00, v01);
                *(uint32_t*)(C + (size_t)(r0 + 8) * N + base16 + poff) = h2(v10, v11);
            }
        }
    }
}

// ---------------- fp16 tensor-core flash attention + residual ------------------
// 128 q-rows per CTA, 8 warps (m16 each). K and V^T double-buffered (8KB tiles).
// No online max; p = ex2.f16x2(S) packed directly into A-fragments;
// row sums accumulated by an extra mma against a ones B-fragment (fp32 accum).
// smem: K0@0 K1@8192 | VT0@16384 VT1@24576 -> 32KB
#define AK0  0
#define AVT0 16384
#define ATT_SMEM 32768

__global__ __launch_bounds__(256, 2)
void attn_kernel(const float* __restrict__ x, float* __restrict__ x1,
                 __half* __restrict__ x1r)
{
    extern __shared__ char sm[];
    const uint32_t sbase = smem_u32(sm);

    const int qt = gridDim.x - 1 - blockIdx.x;   // heavy tiles first
    const int bh = blockIdx.y;
    const int b = bh >> 4, h = bh & 15;
    const int tid = threadIdx.x, lane = tid & 31, w = tid >> 5;
    const int g = lane >> 2, c = lane & 3;

    const size_t headoff = (size_t)b * T * H + (size_t)h * HD;
    const __half* Qg  = g_q + headoff;
    const __half* Kg  = g_k + headoff;
    const __half* VTg = g_vt + (size_t)bh * HD * T;

    const int lrow = tid >> 2;            // 0..63
    const int lch0 = (tid & 3) * 2;
    uint32_t lso[2];
    #pragma unroll
    for (int i = 0; i < 2; i++)
        lso[i] = (uint32_t)(lrow * 128 + (((lch0 + i) ^ (lrow & 7)) << 4));
    const __half* kgp  = Kg  + (size_t)lrow * H + lch0 * 8;
    const __half* vtgp = VTg + (size_t)lrow * T + lch0 * 8;

    const int nkt = 2 * qt + 2;

    #pragma unroll
    for (int i = 0; i < 2; i++) {
        asm volatile("cp.async.cg.shared.global [%0], [%1], 16;"
                     :: "r"(sbase + AK0 + lso[i]), "l"(kgp + i * 8) : "memory");
        asm volatile("cp.async.cg.shared.global [%0], [%1], 16;"
                     :: "r"(sbase + AVT0 + lso[i]), "l"(vtgp + i * 8) : "memory");
    }
    asm volatile("cp.async.commit_group;" ::: "memory");

    uint32_t qa[4][4];
    {
        const int r0 = qt * 128 + w * 16 + g;
        const __half* q0 = Qg + (size_t)r0 * H;
        #pragma unroll
        for (int s = 0; s < 4; s++) {
            uint2 t0 = *(const uint2*)(q0 + s * 16 + c * 4);
            uint2 t1 = *(const uint2*)(q0 + 8 * H + s * 16 + c * 4);
            qa[s][0] = t0.x; qa[s][1] = t1.x; qa[s][2] = t0.y; qa[s][3] = t1.y;
        }
    }

    float o[8][4];
    #pragma unroll
    for (int nt = 0; nt < 8; nt++)
        #pragma unroll
        for (int r = 0; r < 4; r++) o[nt][r] = 0.0f;
    float lacc[4] = {0.0f, 0.0f, 0.0f, 0.0f};    // row sums via ones-mma
    const uint32_t ONES = 0x3C003C00u;           // (1.0h, 1.0h)

    const int rowlo = qt * 128 + w * 16;
    const int row0 = rowlo + g;
    uint32_t coff[4];
    #pragma unroll
    for (int s = 0; s < 4; s++)
        coff[s] = (uint32_t)((((2 * s + (c >> 1)) ^ g) << 4) + (c & 1) * 8);

    for (int kt = 0; kt < nkt; kt++) {
        const uint32_t buf = (kt & 1) ? 8192u : 0u;
        asm volatile("cp.async.wait_group 0;" ::: "memory");
        __syncthreads();

        if (kt + 1 < nkt) {
            const uint32_t nb = (kt & 1) ? 0u : 8192u;
            const __half* ks = kgp  + (size_t)(kt + 1) * 64 * H;
            const __half* vs = vtgp + (kt + 1) * 64;
            #pragma unroll
            for (int i = 0; i < 2; i++) {
                asm volatile("cp.async.cg.shared.global [%0], [%1], 16;"
                             :: "r"(sbase + AK0 + nb + lso[i]), "l"(ks + i * 8) : "memory");
                asm volatile("cp.async.cg.shared.global [%0], [%1], 16;"
                             :: "r"(sbase + AVT0 + nb + lso[i]), "l"(vs + i * 8) : "memory");
            }
        }
        asm volatile("cp.async.commit_group;" ::: "memory");

        const int ktbase = kt * 64;
        const bool active = (ktbase <= rowlo + 15);
        if (active) {
            const uint32_t kbuf  = sbase + AK0 + buf;
            const uint32_t vtbuf = sbase + AVT0 + buf;

            // S = Q @ K^T (S pre-scaled by log2e via q)
            float sacc[8][4];
            #pragma unroll
            for (int nt = 0; nt < 8; nt++)
                #pragma unroll
                for (int r = 0; r < 4; r++) sacc[nt][r] = 0.0f;
            #pragma unroll
            for (int s = 0; s < 4; s++) {
                uint2 bf[8];
                #pragma unroll
                for (int nt = 0; nt < 8; nt++)
                    bf[nt] = lds64(kbuf + (uint32_t)((nt * 8 + g) * 128) + coff[s]);
                #pragma unroll
                for (int nt = 0; nt < 8; nt++)
                    mma16(sacc[nt], qa[s][0], qa[s][1], qa[s][2], qa[s][3],
                          bf[nt].x, bf[nt].y);
            }

            if (ktbase + 63 > rowlo) {
                #pragma unroll
                for (int nt = 0; nt < 8; nt++) {
                    const int colb = ktbase + nt * 8 + 2 * c;
                    if (colb     > row0)     sacc[nt][0] = -30000.0f;
                    if (colb + 1 > row0)     sacc[nt][1] = -30000.0f;
                    if (colb     > row0 + 8) sacc[nt][2] = -30000.0f;
                    if (colb + 1 > row0 + 8) sacc[nt][3] = -30000.0f;
                }
            }

            // p = exp2(S) in fp16x2, packed straight into A-fragment registers
            uint32_t pa[8][2];
            #pragma unroll
            for (int nt = 0; nt < 8; nt++) {
                pa[nt][0] = ex2_h2(cvt_f16x2(sacc[nt][0], sacc[nt][1]));
                pa[nt][1] = ex2_h2(cvt_f16x2(sacc[nt][2], sacc[nt][3]));
            }

            // O += P @ V, and l += P @ ones (fp32 accumulation of the same fp16 P)
            #pragma unroll
            for (int kb = 0; kb < 4; kb++) {
                const uint32_t a0 = pa[2 * kb][0];
                const uint32_t a1 = pa[2 * kb][1];
                const uint32_t a2 = pa[2 * kb + 1][0];
                const uint32_t a3 = pa[2 * kb + 1][1];
                mma16(lacc, a0, a1, a2, a3, ONES, ONES);
                #pragma unroll
                for (int nt = 0; nt < 8; nt++) {
                    const uint2 vb = lds64(vtbuf + (uint32_t)((nt * 8 + g) * 128) + coff[kb]);
                    mma16(o[nt], a0, a1, a2, a3, vb.x, vb.y);
                }
            }
        }
    }

    // lacc[0] = full row sum for row0, lacc[2] = for row0+8 (all columns equal)
    const float inv0 = 1.0f / lacc[0];
    const float inv1 = 1.0f / lacc[2];
    const size_t rb0 = (size_t)b * T * H + (size_t)row0 * H + (size_t)h * HD;
    const size_t rb1 = rb0 + 8 * H;
    #pragma unroll
    for (int nt = 0; nt < 8; nt++) {
        const int d0 = nt * 8 + 2 * c;
        const float v00 = o[nt][0] * inv0 + x[rb0 + d0];
        const float v01 = o[nt][1] * inv0 + x[rb0 + d0 + 1];
        const float v10 = o[nt][2] * inv1 + x[rb1 + d0];
        const float v11 = o[nt][3] * inv1 + x[rb1 + d0 + 1];
        float2 t0; t0.x = v00; t0.y = v01;
        float2 t1; t1.x = v10; t1.y = v11;
        *(float2*)(x1 + rb0 + d0) = t0;
        *(float2*)(x1 + rb1 + d0) = t1;
        const int poff = (nt >> 1) * 16 + 4 * c + 2 * (nt & 1);
        *(uint32_t*)(x1r + rb0 + poff) = h2(v00, v01);
        *(uint32_t*)(x1r + rb1 + poff) = h2(v10, v11);
    }
}

// ---------------- launch -----------------------------------------------------
extern "C" void kernel_launch(void* const* d_in, const int* in_sizes, int n_in,
                              void* d_out, int out_size)
{
    const float* x  = (const float*)d_in[0];
    const float* Wq = (const float*)d_in[1];
    const float* bq = (const float*)d_in[2];
    const float* Wk = (const float*)d_in[3];
    const float* bk = (const float*)d_in[4];
    const float* Wv = (const float*)d_in[5];
    const float* bv = (const float*)d_in[6];
    const float* W1 = (const float*)d_in[7];
    const float* b1 = (const float*)d_in[8];
    const float* W2 = (const float*)d_in[9];
    const float* b2 = (const float*)d_in[10];
    float* out = (float*)d_out;

    __half *q, *k, *vt, *x1r, *xr, *h, *wqt, *wkt, *wvt, *w1t, *w2t;
    float *x1;
    cudaGetSymbolAddress((void**)&q,    g_q);
    cudaGetSymbolAddress((void**)&k,    g_k);
    cudaGetSymbolAddress((void**)&vt,   g_vt);
    cudaGetSymbolAddress((void**)&x1,   g_x1);
    cudaGetSymbolAddress((void**)&x1r,  g_x1r);
    cudaGetSymbolAddress((void**)&xr,   g_xr);
    cudaGetSymbolAddress((void**)&h,    g_h);
    cudaGetSymbolAddress((void**)&wqt,  g_wqt);
    cudaGetSymbolAddress((void**)&wkt,  g_wkt);
    cudaGetSymbolAddress((void**)&wvt,  g_wvt);
    cudaGetSymbolAddress((void**)&w1t,  g_w1t);
    cudaGetSymbolAddress((void**)&w2t,  g_w2t);

    round_perm_k<<<(BT * H) / (256 * 16), 256>>>(x, xr, BT * H);
    transpose_all<<<11264, dim3(32, 8)>>>(Wq, Wk, Wv, W1, W2, wqt, wkt, wvt, w1t, w2t);

    cudaFuncSetAttribute(gemm_fp16, cudaFuncAttributeMaxDynamicSharedMemorySize, GEMM_SMEM);

    // QKV (q: fp16 perm + log2e/32 scale; k: fp16 perm; v -> V^T fp16)
    gemm_fp16<<<dim3(H / 256, BT / 128, 3), 256, GEMM_SMEM>>>(
        xr, wqt, wkt, wvt, bq, bk, bv, q, k, nullptr, nullptr, vt, H, H, 3);

    cudaFuncSetAttribute(attn_kernel, cudaFuncAttributeMaxDynamicSharedMemorySize, ATT_SMEM);
    attn_kernel<<<dim3(T / 128, BATCH * NHEAD), 256, ATT_SMEM>>>(x, x1, x1r);

    // MLP1: h = fp16(gelu(x1r @ W1t^T + b1)), perm16 cols
    gemm_fp16<<<dim3(FF / 256, BT / 128, 1), 256, GEMM_SMEM>>>(
        x1r, w1t, w1t, w1t, b1, b1, b1, h, h, h, nullptr, nullptr, H, FF, 1);

    // MLP2: out = h @ W2t^T + b2 + x1  (fp32 out)
    gemm_fp16<<<dim3(H / 256, BT / 128, 1), 256, GEMM_SMEM>>>(
        h, w2t, w2t, w2t, b2, b2, b2, out, out, out, x1, nullptr, FF, H, 2);
}